// round 2
// baseline (speedup 1.0000x reference)
#include <cuda_runtime.h>
#include <math.h>

#define TT   128
#define BB   512
#define HH   128
#define EMBD 300
#define DD   256
#define G3   384
#define EPSF 1e-7f

__device__ float g_xp_f[TT * BB * G3];
__device__ float g_xp_b[TT * BB * G3];
__device__ float g_ys_f[TT * BB * HH];
__device__ float g_ys_b[TT * BB * HH];
__device__ float g_hyp[TT * BB * DD];
__device__ float g_scores[TT * BB];
__device__ float g_rr2[TT * BB];

// ============================================================
// K1: embed gather + input projections. M=65536,N=768,K=300
// block: one t, 64 batch rows, 128 cols; 256 thr, 4x8 tile
// ============================================================
__global__ __launch_bounds__(256) void k1_inproj(
    const int* __restrict__ tokens, const float* __restrict__ emb,
    const float* __restrict__ Wf, const float* __restrict__ bfv,
    const float* __restrict__ Wb, const float* __restrict__ bbv)
{
    extern __shared__ float sm[];
    float* xT = sm;               // [300][68]
    float* Ws = sm + 300 * 68;    // [100][132]
    __shared__ int tk[64];

    const int tid  = threadIdx.x;
    const int row0 = blockIdx.x * 64;
    const int t    = row0 >> 9;
    const int b0   = row0 & 511;
    const int coff = blockIdx.y * 128;

    if (tid < 64) tk[tid] = tokens[row0 + tid];
    __syncthreads();

    {
        const int rg = tid >> 5, lane = tid & 31;
        for (int r = rg; r < 64; r += 8) {
            const float* e = emb + (long long)tk[r] * EMBD;
            for (int k = lane; k < EMBD; k += 32)
                xT[k * 68 + r] = e[k];
        }
    }

    const bool fwd = (coff < G3);
    const float* Wsrc = fwd ? Wf : Wb;
    const float* bsrc = fwd ? bfv : bbv;
    const int cbase = fwd ? coff : (coff - G3);

    float acc[4][8];
    #pragma unroll
    for (int i = 0; i < 4; i++)
        #pragma unroll
        for (int j = 0; j < 8; j++) acc[i][j] = 0.f;

    const int tr = tid >> 4, tc = tid & 15;
    const float4* xT4 = (const float4*)xT;
    const float4* Ws4 = (const float4*)Ws;

    for (int kc = 0; kc < 3; kc++) {
        __syncthreads();
        {
            const int cg = tid >> 5, lane = tid & 31;
            for (int c = cg; c < 128; c += 8) {
                const float* wrow = Wsrc + (long long)(cbase + c) * EMBD + kc * 100;
                for (int k = lane; k < 100; k += 32)
                    Ws[k * 132 + c] = wrow[k];
            }
        }
        __syncthreads();
        #pragma unroll 4
        for (int k = 0; k < 100; k++) {
            float4 a  = xT4[(kc * 100 + k) * 17 + tr];
            float4 w0 = Ws4[k * 33 + tc];
            float4 w1 = Ws4[k * 33 + 16 + tc];
            float av[4] = {a.x, a.y, a.z, a.w};
            float wv[8] = {w0.x, w0.y, w0.z, w0.w, w1.x, w1.y, w1.z, w1.w};
            #pragma unroll
            for (int i = 0; i < 4; i++)
                #pragma unroll
                for (int j = 0; j < 8; j++)
                    acc[i][j] += av[i] * wv[j];
        }
    }

    #pragma unroll
    for (int j = 0; j < 8; j++) {
        const int c = (j < 4) ? (tc * 4 + j) : (64 + tc * 4 + (j - 4));
        const float bv = bsrc[cbase + c];
        #pragma unroll
        for (int i = 0; i < 4; i++) {
            const int b = b0 + tr * 4 + i;
            const float v = acc[i][j] + bv;
            if (fwd)
                g_xp_f[((long long)t * BB + b) * G3 + cbase + c] = v;
            else
                g_xp_b[((long long)(TT - 1 - t) * BB + b) * G3 + cbase + c] = v;
        }
    }
}

// ============================================================
// K2: GRU scan. 128 blocks x 384 thr; thread j owns W_hh row j.
// ============================================================
__global__ __launch_bounds__(384, 1) void k2_scan(
    const float* __restrict__ hidden,
    const float* __restrict__ Whh_f, const float* __restrict__ bhh_f,
    const float* __restrict__ Whh_b, const float* __restrict__ bhh_b)
{
    __shared__ __align__(16) float hs[8 * 128];
    __shared__ float sg[256 * 9];

    const int tid = threadIdx.x;
    const int dir = blockIdx.x >> 6;
    const int b0  = (blockIdx.x & 63) * 8;

    const float* Whh = dir ? Whh_b : Whh_f;
    const float* bhh = dir ? bhh_b : bhh_f;
    const float* xp  = dir ? g_xp_b : g_xp_f;
    float* ys        = dir ? g_ys_b : g_ys_f;

    float4 w[32];
    #pragma unroll
    for (int i = 0; i < 32; i++)
        w[i] = *(const float4*)&Whh[tid * 128 + i * 4];
    const float bj = bhh[tid];

    if (tid < 128) {
        #pragma unroll
        for (int r = 0; r < 8; r++)
            hs[r * 128 + tid] = hidden[((long long)dir * BB + b0 + r) * HH + tid];
    }
    __syncthreads();

    const float4* h4 = (const float4*)hs;

    for (int t = 0; t < TT; t++) {
        float xpv[8];
        const float* xpt = xp + ((long long)t * BB + b0) * G3 + tid;
        #pragma unroll
        for (int r = 0; r < 8; r++) xpv[r] = xpt[r * (long long)G3];

        float acc[8];
        #pragma unroll
        for (int r = 0; r < 8; r++) acc[r] = 0.f;

        #pragma unroll
        for (int i = 0; i < 32; i++) {
            const float4 wi = w[i];
            #pragma unroll
            for (int r = 0; r < 8; r++) {
                const float4 hv = h4[r * 32 + i];
                acc[r] += wi.x * hv.x + wi.y * hv.y + wi.z * hv.z + wi.w * hv.w;
            }
        }

        if (tid < 256) {
            #pragma unroll
            for (int r = 0; r < 8; r++) {
                const float x = xpv[r] + acc[r] + bj;
                sg[tid * 9 + r] = __fdividef(1.f, 1.f + __expf(-x));
            }
        }
        __syncthreads();
        if (tid >= 256) {
            const int k = tid - 256;
            float* ysrow = ys + ((long long)t * BB + b0) * HH + k;
            #pragma unroll
            for (int r = 0; r < 8; r++) {
                const float rg = sg[k * 9 + r];
                const float zg = sg[(128 + k) * 9 + r];
                const float a  = xpv[r] + rg * (acc[r] + bj);
                const float e  = __expf(2.f * a);
                const float n  = 1.f - __fdividef(2.f, e + 1.f);
                const float ho = hs[r * 128 + k];
                const float hnew = (1.f - zg) * n + zg * ho;
                hs[r * 128 + k] = hnew;
                ysrow[r * (long long)HH] = hnew;
            }
        }
        __syncthreads();
    }
}

// ============================================================
// K3: hyp = tanh(f @ attn2_W^T + b) + ||f||^2. M=65536,N=256,K=256
// ============================================================
__global__ __launch_bounds__(256) void k3_attn(
    const float* __restrict__ W, const float* __restrict__ bias)
{
    extern __shared__ float sm[];
    float* fT = sm;               // [256][68]
    float* Ws = sm + 256 * 68;    // [128][132]

    const int tid  = threadIdx.x;
    const int row0 = blockIdx.x * 64;
    const int t    = row0 >> 9;
    const int b0   = row0 & 511;
    const int tb   = TT - 1 - t;
    const int coff = blockIdx.y * 128;

    {
        const int rg = tid >> 5, lane = tid & 31;
        for (int r = rg; r < 64; r += 8) {
            const float* yf = g_ys_f + ((long long)t * BB + b0 + r) * HH;
            const float* yb = g_ys_b + ((long long)tb * BB + b0 + r) * HH;
            for (int k = lane; k < HH; k += 32) {
                fT[k * 68 + r]        = yf[k];
                fT[(k + HH) * 68 + r] = yb[k];
            }
        }
    }
    __syncthreads();

    if (blockIdx.y == 0) {
        const int r = tid >> 2, q = tid & 3;
        float s = 0.f;
        #pragma unroll 8
        for (int k = q * 64; k < q * 64 + 64; k++) {
            const float v = fT[k * 68 + r];
            s += v * v;
        }
        s += __shfl_xor_sync(0xffffffffu, s, 1);
        s += __shfl_xor_sync(0xffffffffu, s, 2);
        if (q == 0) g_rr2[row0 + r] = s;
    }

    float acc[4][8];
    #pragma unroll
    for (int i = 0; i < 4; i++)
        #pragma unroll
        for (int j = 0; j < 8; j++) acc[i][j] = 0.f;

    const int tr = tid >> 4, tc = tid & 15;
    const float4* fT4 = (const float4*)fT;
    const float4* Ws4 = (const float4*)Ws;

    for (int kc = 0; kc < 2; kc++) {
        __syncthreads();
        {
            const int cg = tid >> 5, lane = tid & 31;
            for (int c = cg; c < 128; c += 8) {
                const float* wrow = W + (long long)(coff + c) * DD + kc * 128;
                for (int k = lane; k < 128; k += 32)
                    Ws[k * 132 + c] = wrow[k];
            }
        }
        __syncthreads();
        #pragma unroll 4
        for (int k = 0; k < 128; k++) {
            float4 a  = fT4[(kc * 128 + k) * 17 + tr];
            float4 w0 = Ws4[k * 33 + tc];
            float4 w1 = Ws4[k * 33 + 16 + tc];
            float av[4] = {a.x, a.y, a.z, a.w};
            float wv[8] = {w0.x, w0.y, w0.z, w0.w, w1.x, w1.y, w1.z, w1.w};
            #pragma unroll
            for (int i = 0; i < 4; i++)
                #pragma unroll
                for (int j = 0; j < 8; j++)
                    acc[i][j] += av[i] * wv[j];
        }
    }

    #pragma unroll
    for (int j = 0; j < 8; j++) {
        const int c = coff + ((j < 4) ? (tc * 4 + j) : (64 + tc * 4 + (j - 4)));
        const float bv = bias[c];
        #pragma unroll
        for (int i = 0; i < 4; i++) {
            float v = acc[i][j] + bv;
            const float e = __expf(2.f * v);
            v = 1.f - __fdividef(2.f, e + 1.f);
            g_hyp[(long long)(row0 + tr * 4 + i) * DD + c] = v;
        }
    }
}

// ============================================================
// K4: hyperbolic scores, one warp per (t,b) row
// ============================================================
__global__ __launch_bounds__(256) void k4_scores(
    const float* __restrict__ cent, const float* __restrict__ beta)
{
    const int row  = blockIdx.x * 8 + (threadIdx.x >> 5);
    const int lane = threadIdx.x & 31;
    const float* hy = g_hyp + (long long)row * DD;

    float h2 = 0.f, cd = 0.f, c2 = 0.f;
    #pragma unroll
    for (int i = 0; i < 8; i++) {
        const float hv = hy[lane + 32 * i];
        const float cv = cent[lane + 32 * i];
        h2 += hv * hv; cd += hv * cv; c2 += cv * cv;
    }
    #pragma unroll
    for (int o = 16; o; o >>= 1) {
        h2 += __shfl_xor_sync(0xffffffffu, h2, o);
        cd += __shfl_xor_sync(0xffffffffu, cd, o);
        c2 += __shfl_xor_sync(0xffffffffu, c2, o);
    }
    if (lane == 0) {
        const float rh = sqrtf(h2), rc = sqrtf(c2);
        float pm = coshf(rh) * coshf(rc) - (sinhf(rh) / rh) * (sinhf(rc) / rc) * cd;
        pm = fminf(fmaxf(pm, 1.f + EPSF), 1e16f);
        const float dist = logf(pm) + log1pf(sqrtf(pm * pm - 1.f + EPSF) / pm);
        g_scores[row] = -beta[0] * dist - 1.f;
    }
}

// ============================================================
// K5: softmax x gamma Einstein-midpoint pooling + h_output
// ============================================================
__global__ __launch_bounds__(256) void k5_pool(float* __restrict__ out)
{
    __shared__ float wk[128];
    __shared__ float red[128];
    const int b = blockIdx.x, tid = threadIdx.x;

    float s = -1e30f;
    if (tid < 128) {
        s = g_scores[tid * BB + b];
        red[tid] = s;
    }
    __syncthreads();
    for (int o = 64; o; o >>= 1) {
        if (tid < o) red[tid] = fmaxf(red[tid], red[tid + o]);
        __syncthreads();
    }
    const float smax = red[0];
    __syncthreads();

    float myw = 0.f, kf = 0.f;
    if (tid < 128) {
        const float rr = sqrtf(g_rr2[tid * BB + b]);
        const float sh = sinhf(rr), ch = coshf(rr);
        const float th = sh / ch;
        float gsq = 1.f - th * th;
        gsq = fminf(fmaxf(gsq, EPSF), 1.f - EPSF);
        float gam = 1.f / sqrtf(gsq);
        gam = fminf(fmaxf(gam, 1.f + EPSF), 1e16f);
        myw = __expf(s - smax) * gam;
        kf = th / rr;
        red[tid] = myw;
    }
    __syncthreads();
    for (int o = 64; o; o >>= 1) {
        if (tid < o) red[tid] += red[tid + o];
        __syncthreads();
    }
    const float wsum = red[0];
    if (tid < 128) wk[tid] = (myw / wsum) * kf;
    __syncthreads();

    float acc = 0.f;
    if (tid < 128) {
        for (int t = 0; t < TT; t++)
            acc += wk[t] * g_ys_f[((long long)t * BB + b) * HH + tid];
    } else {
        const int k = tid - 128;
        for (int t = 0; t < TT; t++)
            acc += wk[t] * g_ys_b[((long long)(TT - 1 - t) * BB + b) * HH + k];
    }
    out[b * DD + tid] = acc;

    float* hout = out + BB * DD;
    if (tid < 128) {
        hout[b * HH + tid] = g_ys_f[((long long)(TT - 1) * BB + b) * HH + tid];
    } else {
        const int k = tid - 128;
        hout[BB * HH + b * HH + k] = g_ys_b[((long long)(TT - 1) * BB + b) * HH + k];
    }
}

// ============================================================
extern "C" void kernel_launch(void* const* d_in, const int* in_sizes, int n_in,
                              void* d_out, int out_size)
{
    const int*   tokens = (const int*)d_in[0];
    const float* hidden = (const float*)d_in[1];
    const float* emb    = (const float*)d_in[2];
    const float* W_ih_f = (const float*)d_in[3];
    const float* W_hh_f = (const float*)d_in[4];
    const float* b_ih_f = (const float*)d_in[5];
    const float* b_hh_f = (const float*)d_in[6];
    const float* W_ih_b = (const float*)d_in[7];
    const float* W_hh_b = (const float*)d_in[8];
    const float* b_ih_b = (const float*)d_in[9];
    const float* b_hh_b = (const float*)d_in[10];
    const float* attn2W = (const float*)d_in[11];
    const float* attn2b = (const float*)d_in[12];
    const float* cent   = (const float*)d_in[13];
    const float* beta   = (const float*)d_in[14];
    float* out = (float*)d_out;

    const int K1_SMEM = (300 * 68 + 100 * 132) * 4;
    const int K3_SMEM = (256 * 68 + 128 * 132) * 4;
    cudaFuncSetAttribute(k1_inproj, cudaFuncAttributeMaxDynamicSharedMemorySize, K1_SMEM);
    cudaFuncSetAttribute(k3_attn,   cudaFuncAttributeMaxDynamicSharedMemorySize, K3_SMEM);

    k1_inproj<<<dim3(1024, 6), 256, K1_SMEM>>>(tokens, emb, W_ih_f, b_ih_f, W_ih_b, b_ih_b);
    k2_scan<<<128, 384>>>(hidden, W_hh_f, b_hh_f, W_hh_b, b_hh_b);
    k3_attn<<<dim3(1024, 2), 256, K3_SMEM>>>(attn2W, attn2b);
    k4_scores<<<8192, 256>>>(cent, beta);
    k5_pool<<<512, 256>>>(out);
}